// round 1
// baseline (speedup 1.0000x reference)
#include <cuda_runtime.h>

// Problem constants (fixed by the reference)
#define N_TOK 2048
#define D_IN  2048
#define D_OUT 2048
#define NE    8
#define NK    4096   // N_TOK * TOPK

// GEMM tiling
#define BM 128
#define BN 128
#define BK 8
#define MAX_TILES 40  // sum_e ceil(cnt_e/BM) < NK/BM + NE = 40

// Device-global scratch (allocation-free per harness rules)
__device__ int   g_num_tiles;
__device__ int   g_tile_expert[MAX_TILES];
__device__ int   g_tile_m0[MAX_TILES];
__device__ int   g_tile_rows[MAX_TILES];
__device__ float g_y[(size_t)NK * D_OUT];   // 32 MB intermediate y_flat

// ---------------------------------------------------------------------------
// Build the tile table from expert_offsets: each tile is <=BM consecutive
// sorted rows belonging to a single expert.
// ---------------------------------------------------------------------------
__global__ void setup_tiles_kernel(const int* __restrict__ expert_offsets) {
    if (threadIdx.x == 0 && blockIdx.x == 0) {
        int nt = 0, prev = 0;
        for (int e = 0; e < NE; e++) {
            int end = expert_offsets[e];
            for (int r = prev; r < end; r += BM) {
                g_tile_expert[nt] = e;
                g_tile_m0[nt]     = r;
                int rem = end - r;
                g_tile_rows[nt]   = rem < BM ? rem : BM;
                nt++;
            }
            prev = end;
        }
        g_num_tiles = nt;
    }
}

// ---------------------------------------------------------------------------
// Grouped GEMM: y[flat, :] = x[flat/2, :] @ W[e].T  for rows in this tile.
// 128x128x8 tile, 256 threads, 8x8 microtile per thread.
// ---------------------------------------------------------------------------
__global__ __launch_bounds__(256, 2)
void grouped_gemm_kernel(const float* __restrict__ x,
                         const float* __restrict__ w,
                         const int*   __restrict__ ssi) {
    const int tile = blockIdx.y;
    if (tile >= g_num_tiles) return;

    const int e    = g_tile_expert[tile];
    const int m0   = g_tile_m0[tile];
    const int rows = g_tile_rows[tile];
    const int n0   = blockIdx.x * BN;

    __shared__ float As[BK][BM];
    __shared__ float Bs[BK][BN];
    __shared__ int   s_flat[BM];

    const int tid = threadIdx.x;

    // Row metadata: flat output index per tile row (-1 = invalid pad row)
    if (tid < BM) {
        s_flat[tid] = (tid < rows) ? ssi[m0 + tid] : -1;
    }
    __syncthreads();

    // Global-load assignment: each thread loads one float4 of A and one of B
    // per k-tile. lr = row within tile (0..127), ls = k offset (0 or 4).
    const int lr = tid >> 1;
    const int ls = (tid & 1) * 4;
    int my_flat = s_flat[lr];
    int tok = ((my_flat >= 0) ? my_flat : s_flat[0]) >> 1;   // TOPK = 2
    const float* a_src = x + (size_t)tok * D_IN + ls;
    const float* b_src = w + ((size_t)e * D_OUT + (size_t)(n0 + lr)) * D_IN + ls;

    const int ty = tid >> 4;   // 0..15  (m direction)
    const int tx = tid & 15;   // 0..15  (n direction)

    float acc[8][8];
    #pragma unroll
    for (int i = 0; i < 8; i++)
        #pragma unroll
        for (int j = 0; j < 8; j++) acc[i][j] = 0.0f;

    for (int k0 = 0; k0 < D_IN; k0 += BK) {
        float4 av = *(const float4*)(a_src + k0);
        float4 bv = *(const float4*)(b_src + k0);

        __syncthreads();   // previous iteration's compute done
        As[ls + 0][lr] = av.x;
        As[ls + 1][lr] = av.y;
        As[ls + 2][lr] = av.z;
        As[ls + 3][lr] = av.w;
        Bs[ls + 0][lr] = bv.x;
        Bs[ls + 1][lr] = bv.y;
        Bs[ls + 2][lr] = bv.z;
        Bs[ls + 3][lr] = bv.w;
        __syncthreads();

        #pragma unroll
        for (int kk = 0; kk < BK; kk++) {
            float4 a0 = *(const float4*)&As[kk][ty * 8];
            float4 a1 = *(const float4*)&As[kk][ty * 8 + 4];
            float4 b0 = *(const float4*)&Bs[kk][tx * 8];
            float4 b1 = *(const float4*)&Bs[kk][tx * 8 + 4];
            float a[8] = {a0.x, a0.y, a0.z, a0.w, a1.x, a1.y, a1.z, a1.w};
            float b[8] = {b0.x, b0.y, b0.z, b0.w, b1.x, b1.y, b1.z, b1.w};
            #pragma unroll
            for (int i = 0; i < 8; i++)
                #pragma unroll
                for (int j = 0; j < 8; j++)
                    acc[i][j] += a[i] * b[j];
        }
    }

    // Epilogue: scatter to y_flat rows
    #pragma unroll
    for (int i = 0; i < 8; i++) {
        int m = ty * 8 + i;
        int flat = s_flat[m];
        if (flat >= 0) {
            float* dst = g_y + (size_t)flat * D_OUT + n0 + tx * 8;
            float4 v0 = make_float4(acc[i][0], acc[i][1], acc[i][2], acc[i][3]);
            float4 v1 = make_float4(acc[i][4], acc[i][5], acc[i][6], acc[i][7]);
            *(float4*)(dst)     = v0;
            *(float4*)(dst + 4) = v1;
        }
    }
}

// ---------------------------------------------------------------------------
// Combine: out[n, :] = gates[n,0]*y[2n, :] + gates[n,1]*y[2n+1, :]
// ---------------------------------------------------------------------------
__global__ void combine_kernel(const float* __restrict__ gates,
                               float* __restrict__ out) {
    int idx = blockIdx.x * blockDim.x + threadIdx.x;   // over N_TOK * D_OUT/4
    int n  = idx >> 9;          // D_OUT/4 = 512
    int d4 = idx & 511;
    float g0 = gates[2 * n];
    float g1 = gates[2 * n + 1];
    const float4* y0 = (const float4*)(g_y + (size_t)(2 * n)     * D_OUT) + d4;
    const float4* y1 = (const float4*)(g_y + (size_t)(2 * n + 1) * D_OUT) + d4;
    float4 a = *y0, b = *y1, o;
    o.x = g0 * a.x + g1 * b.x;
    o.y = g0 * a.y + g1 * b.y;
    o.z = g0 * a.z + g1 * b.z;
    o.w = g0 * a.w + g1 * b.w;
    ((float4*)out)[idx] = o;
}

// ---------------------------------------------------------------------------
// Launch. Input order (metadata): inputs, weight, k, sorted_expert_idxs,
// sorted_scattered_idxs, padded_block_idxs, expert_offsets, gates.
// ---------------------------------------------------------------------------
extern "C" void kernel_launch(void* const* d_in, const int* in_sizes, int n_in,
                              void* d_out, int out_size) {
    const float* x     = (const float*)d_in[0];
    const float* w     = (const float*)d_in[1];
    const int*   ssi   = (const int*)  d_in[4];
    const int*   eoff  = (const int*)  d_in[6];
    const float* gates = (const float*)d_in[7];
    float* out = (float*)d_out;

    setup_tiles_kernel<<<1, 32>>>(eoff);

    dim3 grid(D_OUT / BN, MAX_TILES);
    grouped_gemm_kernel<<<grid, 256>>>(x, w, ssi);

    combine_kernel<<<(N_TOK * (D_OUT / 4)) / 256, 256>>>(gates, out);
}

// round 3
// speedup vs baseline: 2.4555x; 2.4555x over previous
#include <cuda_runtime.h>
#include <cuda_bf16.h>
#include <cstdint>

// Problem constants
#define N_TOK 2048
#define D_IN  2048
#define D_OUT 2048
#define NE    8
#define NK    4096   // N_TOK * TOPK

// Tiling
#define BM 128
#define BN 128
#define KT 32               // fp32 K elements per smem stage
#define NT (D_IN / KT)      // 64 k-iterations
#define MAX_TILES 40

// smem layout (dynamic): s_flat[128] @0, stages @1024
#define SM_FLAT   0
#define SM_TILES  1024
#define TILE_B    8192              // one 128x32 bf16 tile
#define T_AH 0
#define T_AL (1*TILE_B)
#define T_BH (2*TILE_B)
#define T_BL (3*TILE_B)
#define STAGE_BYTES (4*TILE_B)      // 32 KB
#define SMEM_TOTAL (SM_TILES + 2*STAGE_BYTES)   // 66560

// Device scratch
__device__ int   g_num_tiles;
__device__ int   g_tile_expert[MAX_TILES];
__device__ int   g_tile_m0[MAX_TILES];
__device__ int   g_tile_rows[MAX_TILES];
__device__ float g_y[(size_t)NK * D_OUT];   // 32 MB intermediate

// Swizzle for 64B rows: permute 16B chunks by (row>>1)&3 — conflict-free for
// both the STS pattern and ldmatrix.x4 reads (derivation in notes).
__device__ __forceinline__ uint32_t SW(uint32_t off) {
    return off ^ (((off >> 7) & 3u) << 4);
}

__device__ __forceinline__ uint32_t smem_u32(const void* p) {
    uint32_t a;
    asm("{ .reg .u64 t; cvta.to.shared.u64 t, %1; cvt.u32.u64 %0, t; }" : "=r"(a) : "l"(p));
    return a;
}

__device__ __forceinline__ void ldm_x4(uint32_t& r0, uint32_t& r1, uint32_t& r2,
                                       uint32_t& r3, uint32_t addr) {
    asm volatile("ldmatrix.sync.aligned.m8n8.x4.shared.b16 {%0,%1,%2,%3}, [%4];"
                 : "=r"(r0), "=r"(r1), "=r"(r2), "=r"(r3) : "r"(addr));
}

__device__ __forceinline__ void mma_bf16(float* c, const uint32_t* a, const uint32_t* b) {
    asm volatile(
        "mma.sync.aligned.m16n8k16.row.col.f32.bf16.bf16.f32 "
        "{%0,%1,%2,%3}, {%4,%5,%6,%7}, {%8,%9}, {%0,%1,%2,%3};"
        : "+f"(c[0]), "+f"(c[1]), "+f"(c[2]), "+f"(c[3])
        : "r"(a[0]), "r"(a[1]), "r"(a[2]), "r"(a[3]), "r"(b[0]), "r"(b[1]));
}

// ---------------------------------------------------------------------------
__global__ void setup_tiles_kernel(const int* __restrict__ expert_offsets) {
    if (threadIdx.x == 0 && blockIdx.x == 0) {
        int nt = 0, prev = 0;
        for (int e = 0; e < NE; e++) {
            int end = expert_offsets[e];
            for (int r = prev; r < end; r += BM) {
                g_tile_expert[nt] = e;
                g_tile_m0[nt]     = r;
                int rem = end - r;
                g_tile_rows[nt]   = rem < BM ? rem : BM;
                nt++;
            }
            prev = end;
        }
        g_num_tiles = nt;
    }
}

// Split 8 floats into bf16 hi/lo 16B chunks and STS both
__device__ __forceinline__ void split_sts(uint32_t dst_h, uint32_t dst_l,
                                          float4 v0, float4 v1) {
    __nv_bfloat162 h0 = __floats2bfloat162_rn(v0.x, v0.y);
    __nv_bfloat162 h1 = __floats2bfloat162_rn(v0.z, v0.w);
    __nv_bfloat162 h2 = __floats2bfloat162_rn(v1.x, v1.y);
    __nv_bfloat162 h3 = __floats2bfloat162_rn(v1.z, v1.w);
    float2 f0 = __bfloat1622float2(h0), f1 = __bfloat1622float2(h1);
    float2 f2 = __bfloat1622float2(h2), f3 = __bfloat1622float2(h3);
    __nv_bfloat162 l0 = __floats2bfloat162_rn(v0.x - f0.x, v0.y - f0.y);
    __nv_bfloat162 l1 = __floats2bfloat162_rn(v0.z - f1.x, v0.w - f1.y);
    __nv_bfloat162 l2 = __floats2bfloat162_rn(v1.x - f2.x, v1.y - f2.y);
    __nv_bfloat162 l3 = __floats2bfloat162_rn(v1.z - f3.x, v1.w - f3.y);
    asm volatile("st.shared.v4.b32 [%0], {%1,%2,%3,%4};" :: "r"(dst_h),
        "r"(*(uint32_t*)&h0), "r"(*(uint32_t*)&h1),
        "r"(*(uint32_t*)&h2), "r"(*(uint32_t*)&h3) : "memory");
    asm volatile("st.shared.v4.b32 [%0], {%1,%2,%3,%4};" :: "r"(dst_l),
        "r"(*(uint32_t*)&l0), "r"(*(uint32_t*)&l1),
        "r"(*(uint32_t*)&l2), "r"(*(uint32_t*)&l3) : "memory");
}

// ---------------------------------------------------------------------------
// Grouped GEMM via mma.sync bf16x3 (HMMA), 128x128 tile / CTA
// ---------------------------------------------------------------------------
__global__ __launch_bounds__(256)
void moe_gemm_mma(const float* __restrict__ x,
                  const float* __restrict__ w,
                  const int*   __restrict__ ssi) {
    const int tile = blockIdx.y;
    if (tile >= g_num_tiles) return;

    const int e    = g_tile_expert[tile];
    const int m0   = g_tile_m0[tile];
    const int rows = g_tile_rows[tile];
    const int n0   = blockIdx.x * BN;

    extern __shared__ char smem[];
    const uint32_t sb = smem_u32(smem);
    const int tid  = threadIdx.x;
    const int wid  = tid >> 5;
    const int lane = tid & 31;
    const int warp_m = wid & 3;        // 4 warps along M (32 rows each)
    const int warp_n = wid >> 2;       // 2 warps along N (64 cols each)

    int* s_flat = (int*)(smem + SM_FLAT);
    if (tid < BM) s_flat[tid] = (tid < rows) ? ssi[m0 + tid] : -1;
    __syncthreads();

    // --- global loader assignment: row r, k-half kb (16 floats) ---
    const int r  = tid >> 1;
    const int kb = (tid & 1) * 16;
    const int fl = s_flat[r];
    const int tok = ((fl >= 0) ? fl : s_flat[0]) >> 1;     // TOPK=2
    const float* aptr = x + (size_t)tok * D_IN + kb;
    const float* bptr = w + ((size_t)e * D_OUT + (size_t)(n0 + r)) * D_IN + kb;

    // STS addresses (within a tile): row r, chunks c0 = (tid&1)*2, c0+1
    const uint32_t st_off0 = SW((uint32_t)(r * 64 + (tid & 1) * 32));
    const uint32_t st_off1 = SW((uint32_t)(r * 64 + (tid & 1) * 32 + 16));

    // ldmatrix lane-address offsets (within a tile), per k16 step s:
    // A atom i: row = warp_m*32 + i*16 + (lane&7) + ((lane>>3)&1)*8, chunk = s*2 + (lane>>4)
    // B pair (j,j+1): row = warp_n*64 + (j + (lane>>4))*8 + (lane&7), chunk = s*2 + ((lane>>3)&1)
    uint32_t a_off[2][2], b_off[2][4];   // [s][atom/pair]
    #pragma unroll
    for (int s = 0; s < 2; s++) {
        #pragma unroll
        for (int i = 0; i < 2; i++) {
            int arow = warp_m * 32 + i * 16 + (lane & 7) + ((lane >> 3) & 1) * 8;
            int ach  = s * 2 + (lane >> 4);
            a_off[s][i] = SW((uint32_t)(arow * 64 + ach * 16));
        }
        #pragma unroll
        for (int jp = 0; jp < 4; jp++) {
            int brow = warp_n * 64 + (jp * 2 + (lane >> 4)) * 8 + (lane & 7);
            int bch  = s * 2 + ((lane >> 3) & 1);
            b_off[s][jp] = SW((uint32_t)(brow * 64 + bch * 16));
        }
    }

    float acc[2][8][4];
    #pragma unroll
    for (int i = 0; i < 2; i++)
        #pragma unroll
        for (int j = 0; j < 8; j++)
            #pragma unroll
            for (int q = 0; q < 4; q++) acc[i][j][q] = 0.0f;

    float4 ra[4], rb[4];
    #pragma unroll
    for (int q = 0; q < 4; q++) {
        ra[q] = *(const float4*)(aptr + 4 * q);
        rb[q] = *(const float4*)(bptr + 4 * q);
    }

    // store stage 0
    {
        uint32_t stg = sb + SM_TILES;
        split_sts(stg + T_AH + st_off0, stg + T_AL + st_off0, ra[0], ra[1]);
        split_sts(stg + T_AH + st_off1, stg + T_AL + st_off1, ra[2], ra[3]);
        split_sts(stg + T_BH + st_off0, stg + T_BL + st_off0, rb[0], rb[1]);
        split_sts(stg + T_BH + st_off1, stg + T_BL + st_off1, rb[2], rb[3]);
    }
    __syncthreads();

    for (int it = 0; it < NT; it++) {
        // prefetch next k-tile into registers
        if (it + 1 < NT) {
            const int k0 = (it + 1) * KT;
            #pragma unroll
            for (int q = 0; q < 4; q++) {
                ra[q] = *(const float4*)(aptr + k0 + 4 * q);
                rb[q] = *(const float4*)(bptr + k0 + 4 * q);
            }
        }

        // compute on stage it&1
        const uint32_t stg = sb + SM_TILES + (uint32_t)(it & 1) * STAGE_BYTES;
        #pragma unroll
        for (int s = 0; s < 2; s++) {
            uint32_t ah[2][4], al[2][4], bh[4][4], bl[4][4];
            #pragma unroll
            for (int i = 0; i < 2; i++) {
                ldm_x4(ah[i][0], ah[i][1], ah[i][2], ah[i][3], stg + T_AH + a_off[s][i]);
                ldm_x4(al[i][0], al[i][1], al[i][2], al[i][3], stg + T_AL + a_off[s][i]);
            }
            #pragma unroll
            for (int jp = 0; jp < 4; jp++) {
                ldm_x4(bh[jp][0], bh[jp][1], bh[jp][2], bh[jp][3], stg + T_BH + b_off[s][jp]);
                ldm_x4(bl[jp][0], bl[jp][1], bl[jp][2], bl[jp][3], stg + T_BL + b_off[s][jp]);
            }
            #pragma unroll
            for (int i = 0; i < 2; i++) {
                #pragma unroll
                for (int jp = 0; jp < 4; jp++) {
                    // atom 2*jp   : bh[jp][0..1]; atom 2*jp+1: bh[jp][2..3]
                    mma_bf16(acc[i][2 * jp],     ah[i], &bh[jp][0]);
                    mma_bf16(acc[i][2 * jp + 1], ah[i], &bh[jp][2]);
                    mma_bf16(acc[i][2 * jp],     ah[i], &bl[jp][0]);
                    mma_bf16(acc[i][2 * jp + 1], ah[i], &bl[jp][2]);
                    mma_bf16(acc[i][2 * jp],     al[i], &bh[jp][0]);
                    mma_bf16(acc[i][2 * jp + 1], al[i], &bh[jp][2]);
                }
            }
        }

        __syncthreads();   // everyone done reading the other stage's next slot
        if (it + 1 < NT) {
            const uint32_t nstg = sb + SM_TILES + (uint32_t)((it + 1) & 1) * STAGE_BYTES;
            split_sts(nstg + T_AH + st_off0, nstg + T_AL + st_off0, ra[0], ra[1]);
            split_sts(nstg + T_AH + st_off1, nstg + T_AL + st_off1, ra[2], ra[3]);
            split_sts(nstg + T_BH + st_off0, nstg + T_BL + st_off0, rb[0], rb[1]);
            split_sts(nstg + T_BH + st_off1, nstg + T_BL + st_off1, rb[2], rb[3]);
            __syncthreads();
        }
    }

    // Epilogue: scatter acc to g_y.  Thread holds, for atom (i,j):
    // rows mrow0 = warp_m*32 + i*16 + lane/4 (+8 for c2,c3)
    // cols n0 + warp_n*64 + j*8 + (lane%4)*2 (+1)
    #pragma unroll
    for (int i = 0; i < 2; i++) {
        const int mr0 = warp_m * 32 + i * 16 + (lane >> 2);
        const int fl0 = s_flat[mr0];
        const int fl1 = s_flat[mr0 + 8];
        #pragma unroll
        for (int j = 0; j < 8; j++) {
            const int col = n0 + warp_n * 64 + j * 8 + (lane & 3) * 2;
            if (fl0 >= 0)
                *(float2*)(g_y + (size_t)fl0 * D_OUT + col) =
                    make_float2(acc[i][j][0], acc[i][j][1]);
            if (fl1 >= 0)
                *(float2*)(g_y + (size_t)fl1 * D_OUT + col) =
                    make_float2(acc[i][j][2], acc[i][j][3]);
        }
    }
}

// ---------------------------------------------------------------------------
__global__ void combine_kernel(const float* __restrict__ gates,
                               float* __restrict__ out) {
    int idx = blockIdx.x * blockDim.x + threadIdx.x;
    int n  = idx >> 9;          // D_OUT/4 = 512
    int d4 = idx & 511;
    float g0 = gates[2 * n];
    float g1 = gates[2 * n + 1];
    const float4* y0 = (const float4*)(g_y + (size_t)(2 * n)     * D_OUT) + d4;
    const float4* y1 = (const float4*)(g_y + (size_t)(2 * n + 1) * D_OUT) + d4;
    float4 a = *y0, b = *y1, o;
    o.x = g0 * a.x + g1 * b.x;
    o.y = g0 * a.y + g1 * b.y;
    o.z = g0 * a.z + g1 * b.z;
    o.w = g0 * a.w + g1 * b.w;
    ((float4*)out)[idx] = o;
}

// ---------------------------------------------------------------------------
extern "C" void kernel_launch(void* const* d_in, const int* in_sizes, int n_in,
                              void* d_out, int out_size) {
    const float* x     = (const float*)d_in[0];
    const float* w     = (const float*)d_in[1];
    const int*   ssi   = (const int*)  d_in[4];
    const int*   eoff  = (const int*)  d_in[6];
    const float* gates = (const float*)d_in[7];
    float* out = (float*)d_out;

    setup_tiles_kernel<<<1, 32>>>(eoff);

    cudaFuncSetAttribute(moe_gemm_mma,
                         cudaFuncAttributeMaxDynamicSharedMemorySize, SMEM_TOTAL);
    dim3 grid(D_OUT / BN, MAX_TILES);
    moe_gemm_mma<<<grid, 256, SMEM_TOTAL>>>(x, w, ssi);

    combine_kernel<<<(N_TOK * (D_OUT / 4)) / 256, 256>>>(gates, out);
}

// round 4
// speedup vs baseline: 4.0404x; 1.6454x over previous
#include <cuda_runtime.h>
#include <cuda_fp16.h>
#include <cstdint>

// Problem constants
#define N_TOK 2048
#define D_IN  2048
#define D_OUT 2048
#define NE    8
#define NK    4096   // N_TOK * TOPK

// Tiling
#define BM 128
#define BN 128
#define KT 32               // K elements per smem stage
#define NT (D_IN / KT)      // 64 k-iterations
#define STAGES 4
#define MAX_TILES 40

// smem: s_flat[128] @0, stages @1024. Tile = 128 rows x 32 fp16 (64B rows).
#define SM_FLAT   0
#define SM_TILES  1024
#define TILE_B    8192
#define T_AH 0
#define T_AL (1*TILE_B)
#define T_BH (2*TILE_B)
#define STAGE_B (3*TILE_B)                      // 24 KB
#define SMEM_TOTAL (SM_TILES + STAGES*STAGE_B)  // 99328

// Device scratch
__device__ __half g_xh[(size_t)N_TOK * D_IN];          // 8 MB
__device__ __half g_xl[(size_t)N_TOK * D_IN];          // 8 MB
__device__ __half g_wh[(size_t)NE * D_OUT * D_IN];     // 64 MB
__device__ float  g_y[(size_t)NK * D_OUT];             // 32 MB

// 64B-row swizzle: permute 16B chunks by (row>>1)&3 (validated in R3)
__device__ __forceinline__ uint32_t SW(uint32_t off) {
    return off ^ (((off >> 7) & 3u) << 4);
}

__device__ __forceinline__ uint32_t smem_u32(const void* p) {
    uint32_t a;
    asm("{ .reg .u64 t; cvta.to.shared.u64 t, %1; cvt.u32.u64 %0, t; }" : "=r"(a) : "l"(p));
    return a;
}

__device__ __forceinline__ void cp16(uint32_t dst, const void* src) {
    asm volatile("cp.async.cg.shared.global [%0], [%1], 16;" :: "r"(dst), "l"(src) : "memory");
}
__device__ __forceinline__ void cp_commit() {
    asm volatile("cp.async.commit_group;" ::: "memory");
}
__device__ __forceinline__ void cp_wait2() {
    asm volatile("cp.async.wait_group 2;" ::: "memory");
}

__device__ __forceinline__ void ldm_x4(uint32_t& r0, uint32_t& r1, uint32_t& r2,
                                       uint32_t& r3, uint32_t addr) {
    asm volatile("ldmatrix.sync.aligned.m8n8.x4.shared.b16 {%0,%1,%2,%3}, [%4];"
                 : "=r"(r0), "=r"(r1), "=r"(r2), "=r"(r3) : "r"(addr));
}

__device__ __forceinline__ void mma_fp16(float* c, const uint32_t* a, const uint32_t* b) {
    asm volatile(
        "mma.sync.aligned.m16n8k16.row.col.f32.f16.f16.f32 "
        "{%0,%1,%2,%3}, {%4,%5,%6,%7}, {%8,%9}, {%0,%1,%2,%3};"
        : "+f"(c[0]), "+f"(c[1]), "+f"(c[2]), "+f"(c[3])
        : "r"(a[0]), "r"(a[1]), "r"(a[2]), "r"(a[3]), "r"(b[0]), "r"(b[1]));
}

// ---------------------------------------------------------------------------
// Prepass: x fp32 -> (xh, xl) fp16 split
// ---------------------------------------------------------------------------
__global__ void conv_x_kernel(const float* __restrict__ x) {
    size_t i = ((size_t)blockIdx.x * blockDim.x + threadIdx.x) * 8;
    float4 v0 = *(const float4*)(x + i);
    float4 v1 = *(const float4*)(x + i + 4);
    __half2 h[4], l[4];
    float vv[8] = {v0.x, v0.y, v0.z, v0.w, v1.x, v1.y, v1.z, v1.w};
    #pragma unroll
    for (int q = 0; q < 4; q++) {
        __half a = __float2half_rn(vv[2*q]);
        __half b = __float2half_rn(vv[2*q+1]);
        h[q] = __halves2half2(a, b);
        l[q] = __halves2half2(__float2half_rn(vv[2*q]   - __half2float(a)),
                              __float2half_rn(vv[2*q+1] - __half2float(b)));
    }
    *(uint4*)(g_xh + i) = *(uint4*)h;
    *(uint4*)(g_xl + i) = *(uint4*)l;
}

// Prepass: W fp32 -> wh fp16 (single rounding; error budget 2.8e-4)
__global__ void conv_w_kernel(const float* __restrict__ w) {
    size_t i = ((size_t)blockIdx.x * blockDim.x + threadIdx.x) * 8;
    float4 v0 = *(const float4*)(w + i);
    float4 v1 = *(const float4*)(w + i + 4);
    __half2 h[4];
    h[0] = __floats2half2_rn(v0.x, v0.y);
    h[1] = __floats2half2_rn(v0.z, v0.w);
    h[2] = __floats2half2_rn(v1.x, v1.y);
    h[3] = __floats2half2_rn(v1.z, v1.w);
    *(uint4*)(g_wh + i) = *(uint4*)h;
}

// ---------------------------------------------------------------------------
// Grouped GEMM: 128x128 tile/CTA, cp.async 4-stage pipeline, fp16x2 HMMA
// ---------------------------------------------------------------------------
__global__ __launch_bounds__(256, 2)
void moe_gemm(const int* __restrict__ ssi,
              const int* __restrict__ eoff) {
    // Per-CTA tile mapping from expert_offsets (no setup kernel)
    const int tile = blockIdx.y;
    int e = -1, m0 = 0, rows = 0;
    {
        int nt = 0, prev = 0;
        #pragma unroll
        for (int ee = 0; ee < NE; ee++) {
            int end = __ldg(eoff + ee);
            int t = (end - prev + BM - 1) >> 7;
            if (e < 0 && tile < nt + t) {
                e = ee;
                m0 = prev + (tile - nt) * BM;
                int rem = end - m0;
                rows = rem < BM ? rem : BM;
            }
            nt += t;
            prev = end;
        }
    }
    if (e < 0) return;
    const int n0 = blockIdx.x * BN;

    extern __shared__ char smem[];
    const uint32_t sb = smem_u32(smem);
    const int tid  = threadIdx.x;
    const int wid  = tid >> 5;
    const int lane = tid & 31;
    const int warp_m = wid & 3;
    const int warp_n = wid >> 2;

    int* s_flat = (int*)(smem + SM_FLAT);
    if (tid < BM) s_flat[tid] = (tid < rows) ? ssi[m0 + tid] : -1;
    __syncthreads();

    // --- cp.async source pointers ---
    // Each thread owns chunks {tid, tid+256} of each 512-chunk tile:
    //   chunk ch -> row = ch>>2, 16B col c = ch&3  (8 fp16 per chunk)
    const int r0 = tid >> 2, r1 = r0 + 64;
    const int c16 = (tid & 3) * 8;          // fp16 element offset of chunk
    int fa0 = s_flat[r0], fa1 = s_flat[r1];
    const int tk0 = ((fa0 >= 0) ? fa0 : s_flat[0]) >> 1;
    const int tk1 = ((fa1 >= 0) ? fa1 : s_flat[0]) >> 1;
    const __half* a0h = g_xh + (size_t)tk0 * D_IN + c16;
    const __half* a1h = g_xh + (size_t)tk1 * D_IN + c16;
    const __half* a0l = g_xl + (size_t)tk0 * D_IN + c16;
    const __half* a1l = g_xl + (size_t)tk1 * D_IN + c16;
    const __half* b0  = g_wh + ((size_t)e * D_OUT + (size_t)(n0 + r0)) * D_IN + c16;
    const __half* b1  = g_wh + ((size_t)e * D_OUT + (size_t)(n0 + r1)) * D_IN + c16;

    const uint32_t d0 = SW((uint32_t)(r0 * 64 + (tid & 3) * 16));
    const uint32_t d1 = SW((uint32_t)(r1 * 64 + (tid & 3) * 16));

    // ldmatrix offsets (within a tile), per k16 step s (layout proven in R3)
    uint32_t a_off[2][2], b_off[2][4];
    #pragma unroll
    for (int s = 0; s < 2; s++) {
        #pragma unroll
        for (int i = 0; i < 2; i++) {
            int arow = warp_m * 32 + i * 16 + (lane & 7) + ((lane >> 3) & 1) * 8;
            int ach  = s * 2 + (lane >> 4);
            a_off[s][i] = SW((uint32_t)(arow * 64 + ach * 16));
        }
        #pragma unroll
        for (int jp = 0; jp < 4; jp++) {
            int brow = warp_n * 64 + (jp * 2 + (lane >> 4)) * 8 + (lane & 7);
            int bch  = s * 2 + ((lane >> 3) & 1);
            b_off[s][jp] = SW((uint32_t)(brow * 64 + bch * 16));
        }
    }

    // Issue one stage's loads (stage slot st, k-tile kt)
    auto issue = [&](int st, int kt) {
        const uint32_t stg = sb + SM_TILES + (uint32_t)st * STAGE_B;
        const int k = kt * KT;
        cp16(stg + T_AH + d0, a0h + k);
        cp16(stg + T_AH + d1, a1h + k);
        cp16(stg + T_AL + d0, a0l + k);
        cp16(stg + T_AL + d1, a1l + k);
        cp16(stg + T_BH + d0, b0 + k);
        cp16(stg + T_BH + d1, b1 + k);
    };

    float acc[2][8][4];
    #pragma unroll
    for (int i = 0; i < 2; i++)
        #pragma unroll
        for (int j = 0; j < 8; j++)
            #pragma unroll
            for (int q = 0; q < 4; q++) acc[i][j][q] = 0.0f;

    // Prologue: fill STAGES-1 stages
    #pragma unroll
    for (int s = 0; s < STAGES - 1; s++) { issue(s, s); cp_commit(); }

    for (int it = 0; it < NT; it++) {
        cp_wait2();          // stage it resident (empty tail groups keep count)
        __syncthreads();

        // refill slot (it+3)%4 for k-tile it+3 (slot consumed at iter it-1)
        if (it + STAGES - 1 < NT) issue((it + STAGES - 1) & (STAGES - 1), it + STAGES - 1);
        cp_commit();

        const uint32_t stg = sb + SM_TILES + (uint32_t)(it & (STAGES - 1)) * STAGE_B;
        #pragma unroll
        for (int s = 0; s < 2; s++) {
            uint32_t ah[2][4], al[2][4], bh[4][4];
            #pragma unroll
            for (int i = 0; i < 2; i++) {
                ldm_x4(ah[i][0], ah[i][1], ah[i][2], ah[i][3], stg + T_AH + a_off[s][i]);
                ldm_x4(al[i][0], al[i][1], al[i][2], al[i][3], stg + T_AL + a_off[s][i]);
            }
            #pragma unroll
            for (int jp = 0; jp < 4; jp++)
                ldm_x4(bh[jp][0], bh[jp][1], bh[jp][2], bh[jp][3], stg + T_BH + b_off[s][jp]);
            #pragma unroll
            for (int i = 0; i < 2; i++) {
                #pragma unroll
                for (int jp = 0; jp < 4; jp++) {
                    mma_fp16(acc[i][2 * jp],     ah[i], &bh[jp][0]);
                    mma_fp16(acc[i][2 * jp + 1], ah[i], &bh[jp][2]);
                    mma_fp16(acc[i][2 * jp],     al[i], &bh[jp][0]);
                    mma_fp16(acc[i][2 * jp + 1], al[i], &bh[jp][2]);
                }
            }
        }
        __syncthreads();     // all warps done with slot (it)%4 before refill next iter
    }

    // Epilogue: scatter to g_y
    #pragma unroll
    for (int i = 0; i < 2; i++) {
        const int mr0 = warp_m * 32 + i * 16 + (lane >> 2);
        const int fl0 = s_flat[mr0];
        const int fl1 = s_flat[mr0 + 8];
        #pragma unroll
        for (int j = 0; j < 8; j++) {
            const int col = n0 + warp_n * 64 + j * 8 + (lane & 3) * 2;
            if (fl0 >= 0)
                *(float2*)(g_y + (size_t)fl0 * D_OUT + col) =
                    make_float2(acc[i][j][0], acc[i][j][1]);
            if (fl1 >= 0)
                *(float2*)(g_y + (size_t)fl1 * D_OUT + col) =
                    make_float2(acc[i][j][2], acc[i][j][3]);
        }
    }
}

// ---------------------------------------------------------------------------
__global__ void combine_kernel(const float* __restrict__ gates,
                               float* __restrict__ out) {
    int idx = blockIdx.x * blockDim.x + threadIdx.x;
    int n  = idx >> 9;
    int d4 = idx & 511;
    float g0 = gates[2 * n];
    float g1 = gates[2 * n + 1];
    const float4* y0 = (const float4*)(g_y + (size_t)(2 * n)     * D_OUT) + d4;
    const float4* y1 = (const float4*)(g_y + (size_t)(2 * n + 1) * D_OUT) + d4;
    float4 a = *y0, b = *y1, o;
    o.x = g0 * a.x + g1 * b.x;
    o.y = g0 * a.y + g1 * b.y;
    o.z = g0 * a.z + g1 * b.z;
    o.w = g0 * a.w + g1 * b.w;
    ((float4*)out)[idx] = o;
}

// ---------------------------------------------------------------------------
extern "C" void kernel_launch(void* const* d_in, const int* in_sizes, int n_in,
                              void* d_out, int out_size) {
    const float* x     = (const float*)d_in[0];
    const float* w     = (const float*)d_in[1];
    const int*   ssi   = (const int*)  d_in[4];
    const int*   eoff  = (const int*)  d_in[6];
    const float* gates = (const float*)d_in[7];
    float* out = (float*)d_out;

    conv_x_kernel<<<(N_TOK * D_IN) / (256 * 8), 256>>>(x);
    conv_w_kernel<<<(NE * D_OUT * D_IN) / (256 * 8), 256>>>(w);

    cudaFuncSetAttribute(moe_gemm,
                         cudaFuncAttributeMaxDynamicSharedMemorySize, SMEM_TOTAL);
    dim3 grid(D_OUT / BN, MAX_TILES);
    moe_gemm<<<grid, 256, SMEM_TOTAL>>>(ssi, eoff);

    combine_kernel<<<(N_TOK * (D_OUT / 4)) / 256, 256>>>(gates, out);
}

// round 5
// speedup vs baseline: 6.4109x; 1.5867x over previous
#include <cuda_runtime.h>
#include <cuda_fp16.h>
#include <cstdint>

// Problem constants
#define N_TOK 2048
#define D_IN  2048
#define D_OUT 2048
#define NE    8
#define NK    4096   // N_TOK * TOPK

// Tiling
#define BM 128
#define BN 128
#define KT 32               // K elements per smem stage
#define NT (D_IN / KT)      // 64 k-iterations
#define STAGES 4
#define MAX_TILES 40

// smem: s_flat[128] @0, stages @1024. Tile = 128 rows x 32 fp16 (64B rows).
#define SM_FLAT   0
#define SM_TILES  1024
#define TILE_B    8192
#define T_AH 0
#define T_BH TILE_B
#define STAGE_B (2*TILE_B)                      // 16 KB
#define SMEM_TOTAL (SM_TILES + STAGES*STAGE_B)  // 66560

// Device scratch
__device__ __half g_xh[(size_t)N_TOK * D_IN];          // 8 MB
__device__ __half g_wh[(size_t)NE * D_OUT * D_IN];     // 64 MB
__device__ float  g_y[(size_t)NK * D_OUT];             // 32 MB

// 64B-row swizzle: permute 16B chunks by (row>>1)&3 (validated R3/R4)
__device__ __forceinline__ uint32_t SW(uint32_t off) {
    return off ^ (((off >> 7) & 3u) << 4);
}

__device__ __forceinline__ uint32_t smem_u32(const void* p) {
    uint32_t a;
    asm("{ .reg .u64 t; cvta.to.shared.u64 t, %1; cvt.u32.u64 %0, t; }" : "=r"(a) : "l"(p));
    return a;
}

__device__ __forceinline__ void cp16(uint32_t dst, const void* src) {
    asm volatile("cp.async.cg.shared.global [%0], [%1], 16;" :: "r"(dst), "l"(src) : "memory");
}
__device__ __forceinline__ void cp_commit() {
    asm volatile("cp.async.commit_group;" ::: "memory");
}
__device__ __forceinline__ void cp_wait2() {
    asm volatile("cp.async.wait_group 2;" ::: "memory");
}

__device__ __forceinline__ void ldm_x4(uint32_t& r0, uint32_t& r1, uint32_t& r2,
                                       uint32_t& r3, uint32_t addr) {
    asm volatile("ldmatrix.sync.aligned.m8n8.x4.shared.b16 {%0,%1,%2,%3}, [%4];"
                 : "=r"(r0), "=r"(r1), "=r"(r2), "=r"(r3) : "r"(addr));
}

__device__ __forceinline__ void mma_fp16(float* c, const uint32_t* a, const uint32_t* b) {
    asm volatile(
        "mma.sync.aligned.m16n8k16.row.col.f32.f16.f16.f32 "
        "{%0,%1,%2,%3}, {%4,%5,%6,%7}, {%8,%9}, {%0,%1,%2,%3};"
        : "+f"(c[0]), "+f"(c[1]), "+f"(c[2]), "+f"(c[3])
        : "r"(a[0]), "r"(a[1]), "r"(a[2]), "r"(a[3]), "r"(b[0]), "r"(b[1]));
}

// ---------------------------------------------------------------------------
// Prepass: fp32 -> fp16 (single rounding each; calibrated err 2.07e-4/operand)
// ---------------------------------------------------------------------------
__global__ void conv_x_kernel(const float* __restrict__ x) {
    size_t i = ((size_t)blockIdx.x * blockDim.x + threadIdx.x) * 8;
    float4 v0 = *(const float4*)(x + i);
    float4 v1 = *(const float4*)(x + i + 4);
    __half2 h[4];
    h[0] = __floats2half2_rn(v0.x, v0.y);
    h[1] = __floats2half2_rn(v0.z, v0.w);
    h[2] = __floats2half2_rn(v1.x, v1.y);
    h[3] = __floats2half2_rn(v1.z, v1.w);
    *(uint4*)(g_xh + i) = *(uint4*)h;
}

__global__ void conv_w_kernel(const float* __restrict__ w) {
    size_t i = ((size_t)blockIdx.x * blockDim.x + threadIdx.x) * 8;
    float4 v0 = *(const float4*)(w + i);
    float4 v1 = *(const float4*)(w + i + 4);
    __half2 h[4];
    h[0] = __floats2half2_rn(v0.x, v0.y);
    h[1] = __floats2half2_rn(v0.z, v0.w);
    h[2] = __floats2half2_rn(v1.x, v1.y);
    h[3] = __floats2half2_rn(v1.z, v1.w);
    *(uint4*)(g_wh + i) = *(uint4*)h;
}

// ---------------------------------------------------------------------------
// Grouped GEMM: 128x128 tile/CTA, cp.async 4-stage pipeline, fp16 HMMA
// ---------------------------------------------------------------------------
__global__ __launch_bounds__(256, 2)
void moe_gemm(const int* __restrict__ ssi,
              const int* __restrict__ eoff) {
    // Per-CTA tile mapping from expert_offsets
    const int tile = blockIdx.y;
    int e = -1, m0 = 0, rows = 0;
    {
        int nt = 0, prev = 0;
        #pragma unroll
        for (int ee = 0; ee < NE; ee++) {
            int end = __ldg(eoff + ee);
            int t = (end - prev + BM - 1) >> 7;
            if (e < 0 && tile < nt + t) {
                e = ee;
                m0 = prev + (tile - nt) * BM;
                int rem = end - m0;
                rows = rem < BM ? rem : BM;
            }
            nt += t;
            prev = end;
        }
    }
    if (e < 0) return;
    const int n0 = blockIdx.x * BN;

    extern __shared__ char smem[];
    const uint32_t sb = smem_u32(smem);
    const int tid  = threadIdx.x;
    const int wid  = tid >> 5;
    const int lane = tid & 31;
    const int warp_m = wid & 3;
    const int warp_n = wid >> 2;

    int* s_flat = (int*)(smem + SM_FLAT);
    if (tid < BM) s_flat[tid] = (tid < rows) ? ssi[m0 + tid] : -1;
    __syncthreads();

    // cp.async: thread owns chunks {tid, tid+256} of each 512-chunk tile
    const int r0 = tid >> 2, r1 = r0 + 64;
    const int c16 = (tid & 3) * 8;
    int fa0 = s_flat[r0], fa1 = s_flat[r1];
    const int tk0 = ((fa0 >= 0) ? fa0 : s_flat[0]) >> 1;
    const int tk1 = ((fa1 >= 0) ? fa1 : s_flat[0]) >> 1;
    const __half* a0h = g_xh + (size_t)tk0 * D_IN + c16;
    const __half* a1h = g_xh + (size_t)tk1 * D_IN + c16;
    const __half* b0  = g_wh + ((size_t)e * D_OUT + (size_t)(n0 + r0)) * D_IN + c16;
    const __half* b1  = g_wh + ((size_t)e * D_OUT + (size_t)(n0 + r1)) * D_IN + c16;

    const uint32_t d0 = SW((uint32_t)(r0 * 64 + (tid & 3) * 16));
    const uint32_t d1 = SW((uint32_t)(r1 * 64 + (tid & 3) * 16));

    // ldmatrix offsets (proven layout)
    uint32_t a_off[2][2], b_off[2][4];
    #pragma unroll
    for (int s = 0; s < 2; s++) {
        #pragma unroll
        for (int i = 0; i < 2; i++) {
            int arow = warp_m * 32 + i * 16 + (lane & 7) + ((lane >> 3) & 1) * 8;
            int ach  = s * 2 + (lane >> 4);
            a_off[s][i] = SW((uint32_t)(arow * 64 + ach * 16));
        }
        #pragma unroll
        for (int jp = 0; jp < 4; jp++) {
            int brow = warp_n * 64 + (jp * 2 + (lane >> 4)) * 8 + (lane & 7);
            int bch  = s * 2 + ((lane >> 3) & 1);
            b_off[s][jp] = SW((uint32_t)(brow * 64 + bch * 16));
        }
    }

    auto issue = [&](int st, int kt) {
        const uint32_t stg = sb + SM_TILES + (uint32_t)st * STAGE_B;
        const int k = kt * KT;
        cp16(stg + T_AH + d0, a0h + k);
        cp16(stg + T_AH + d1, a1h + k);
        cp16(stg + T_BH + d0, b0 + k);
        cp16(stg + T_BH + d1, b1 + k);
    };

    float acc[2][8][4];
    #pragma unroll
    for (int i = 0; i < 2; i++)
        #pragma unroll
        for (int j = 0; j < 8; j++)
            #pragma unroll
            for (int q = 0; q < 4; q++) acc[i][j][q] = 0.0f;

    #pragma unroll
    for (int s = 0; s < STAGES - 1; s++) { issue(s, s); cp_commit(); }

    for (int it = 0; it < NT; it++) {
        cp_wait2();
        __syncthreads();

        if (it + STAGES - 1 < NT) issue((it + STAGES - 1) & (STAGES - 1), it + STAGES - 1);
        cp_commit();

        const uint32_t stg = sb + SM_TILES + (uint32_t)(it & (STAGES - 1)) * STAGE_B;
        #pragma unroll
        for (int s = 0; s < 2; s++) {
            uint32_t ah[2][4], bh[4][4];
            #pragma unroll
            for (int i = 0; i < 2; i++)
                ldm_x4(ah[i][0], ah[i][1], ah[i][2], ah[i][3], stg + T_AH + a_off[s][i]);
            #pragma unroll
            for (int jp = 0; jp < 4; jp++)
                ldm_x4(bh[jp][0], bh[jp][1], bh[jp][2], bh[jp][3], stg + T_BH + b_off[s][jp]);
            #pragma unroll
            for (int i = 0; i < 2; i++) {
                #pragma unroll
                for (int jp = 0; jp < 4; jp++) {
                    mma_fp16(acc[i][2 * jp],     ah[i], &bh[jp][0]);
                    mma_fp16(acc[i][2 * jp + 1], ah[i], &bh[jp][2]);
                }
            }
        }
        __syncthreads();
    }

    // Epilogue: scatter to g_y
    #pragma unroll
    for (int i = 0; i < 2; i++) {
        const int mr0 = warp_m * 32 + i * 16 + (lane >> 2);
        const int fl0 = s_flat[mr0];
        const int fl1 = s_flat[mr0 + 8];
        #pragma unroll
        for (int j = 0; j < 8; j++) {
            const int col = n0 + warp_n * 64 + j * 8 + (lane & 3) * 2;
            if (fl0 >= 0)
                *(float2*)(g_y + (size_t)fl0 * D_OUT + col) =
                    make_float2(acc[i][j][0], acc[i][j][1]);
            if (fl1 >= 0)
                *(float2*)(g_y + (size_t)fl1 * D_OUT + col) =
                    make_float2(acc[i][j][2], acc[i][j][3]);
        }
    }
}

// ---------------------------------------------------------------------------
__global__ void combine_kernel(const float* __restrict__ gates,
                               float* __restrict__ out) {
    int idx = blockIdx.x * blockDim.x + threadIdx.x;
    int n  = idx >> 9;
    int d4 = idx & 511;
    float g0 = gates[2 * n];
    float g1 = gates[2 * n + 1];
    const float4* y0 = (const float4*)(g_y + (size_t)(2 * n)     * D_OUT) + d4;
    const float4* y1 = (const float4*)(g_y + (size_t)(2 * n + 1) * D_OUT) + d4;
    float4 a = *y0, b = *y1, o;
    o.x = g0 * a.x + g1 * b.x;
    o.y = g0 * a.y + g1 * b.y;
    o.z = g0 * a.z + g1 * b.z;
    o.w = g0 * a.w + g1 * b.w;
    ((float4*)out)[idx] = o;
}

// ---------------------------------------------------------------------------
extern "C" void kernel_launch(void* const* d_in, const int* in_sizes, int n_in,
                              void* d_out, int out_size) {
    const float* x     = (const float*)d_in[0];
    const float* w     = (const float*)d_in[1];
    const int*   ssi   = (const int*)  d_in[4];
    const int*   eoff  = (const int*)  d_in[6];
    const float* gates = (const float*)d_in[7];
    float* out = (float*)d_out;

    conv_x_kernel<<<(N_TOK * D_IN) / (256 * 8), 256>>>(x);
    conv_w_kernel<<<(NE * D_OUT * D_IN) / (256 * 8), 256>>>(w);

    cudaFuncSetAttribute(moe_gemm,
                         cudaFuncAttributeMaxDynamicSharedMemorySize, SMEM_TOTAL);
    dim3 grid(D_OUT / BN, MAX_TILES);
    moe_gemm<<<grid, 256, SMEM_TOTAL>>>(ssi, eoff);

    combine_kernel<<<(N_TOK * (D_OUT / 4)) / 256, 256>>>(gates, out);
}

// round 6
// speedup vs baseline: 6.5984x; 1.0292x over previous
#include <cuda_runtime.h>
#include <cuda_fp16.h>
#include <cstdint>

// Problem constants
#define N_TOK 2048
#define D_IN  2048
#define D_OUT 2048
#define NE    8
#define NK    4096

// Tiling
#define BM 128
#define BN 128
#define KT 32
#define NT (D_IN / KT)
#define STAGES 4
#define MAX_TILES 40

// smem: s_flat[128] @0, stages @1024. Tile = 128 rows x 32 fp16 (64B rows).
#define SM_FLAT   0
#define SM_TILES  1024
#define TILE_B    8192
#define T_AH 0
#define T_BH TILE_B
#define STAGE_B (2*TILE_B)                      // 16 KB
#define SMEM_TOTAL (SM_TILES + STAGES*STAGE_B)  // 66560

// Device scratch
__device__ __half g_xh[(size_t)N_TOK * D_IN];          // 8 MB
__device__ __half g_wh[(size_t)NE * D_OUT * D_IN];     // 64 MB
__device__ float  g_y[(size_t)NK * D_OUT];             // 32 MB

__device__ __forceinline__ uint32_t SW(uint32_t off) {
    return off ^ (((off >> 7) & 3u) << 4);
}

__device__ __forceinline__ uint32_t smem_u32(const void* p) {
    uint32_t a;
    asm("{ .reg .u64 t; cvta.to.shared.u64 t, %1; cvt.u32.u64 %0, t; }" : "=r"(a) : "l"(p));
    return a;
}

__device__ __forceinline__ void cp16(uint32_t dst, const void* src) {
    asm volatile("cp.async.cg.shared.global [%0], [%1], 16;" :: "r"(dst), "l"(src) : "memory");
}
__device__ __forceinline__ void cp_commit() {
    asm volatile("cp.async.commit_group;" ::: "memory");
}
__device__ __forceinline__ void cp_wait2() {
    asm volatile("cp.async.wait_group 2;" ::: "memory");
}

__device__ __forceinline__ void ldm_x4(uint32_t& r0, uint32_t& r1, uint32_t& r2,
                                       uint32_t& r3, uint32_t addr) {
    asm volatile("ldmatrix.sync.aligned.m8n8.x4.shared.b16 {%0,%1,%2,%3}, [%4];"
                 : "=r"(r0), "=r"(r1), "=r"(r2), "=r"(r3) : "r"(addr));
}

__device__ __forceinline__ void mma_fp16(float* c, const uint32_t* a, const uint32_t* b) {
    asm volatile(
        "mma.sync.aligned.m16n8k16.row.col.f32.f16.f16.f32 "
        "{%0,%1,%2,%3}, {%4,%5,%6,%7}, {%8,%9}, {%0,%1,%2,%3};"
        : "+f"(c[0]), "+f"(c[1]), "+f"(c[2]), "+f"(c[3])
        : "r"(a[0]), "r"(a[1]), "r"(a[2]), "r"(a[3]), "r"(b[0]), "r"(b[1]));
}

// ---------------------------------------------------------------------------
// Prepass: fp32 -> fp16
// ---------------------------------------------------------------------------
__global__ void conv_x_kernel(const float* __restrict__ x) {
    size_t i = ((size_t)blockIdx.x * blockDim.x + threadIdx.x) * 8;
    float4 v0 = *(const float4*)(x + i);
    float4 v1 = *(const float4*)(x + i + 4);
    __half2 h[4];
    h[0] = __floats2half2_rn(v0.x, v0.y);
    h[1] = __floats2half2_rn(v0.z, v0.w);
    h[2] = __floats2half2_rn(v1.x, v1.y);
    h[3] = __floats2half2_rn(v1.z, v1.w);
    *(uint4*)(g_xh + i) = *(uint4*)h;
}

__global__ void conv_w_kernel(const float* __restrict__ w) {
    size_t i = ((size_t)blockIdx.x * blockDim.x + threadIdx.x) * 8;
    float4 v0 = *(const float4*)(w + i);
    float4 v1 = *(const float4*)(w + i + 4);
    __half2 h[4];
    h[0] = __floats2half2_rn(v0.x, v0.y);
    h[1] = __floats2half2_rn(v0.z, v0.w);
    h[2] = __floats2half2_rn(v1.x, v1.y);
    h[3] = __floats2half2_rn(v1.z, v1.w);
    *(uint4*)(g_wh + i) = *(uint4*)h;
}

// ---------------------------------------------------------------------------
// Grouped GEMM: 128x128 tile/CTA, 4 warps (64x64 warp tile), cp.async x4
// ---------------------------------------------------------------------------
__global__ __launch_bounds__(128, 2)
void moe_gemm(const int* __restrict__ ssi,
              const int* __restrict__ eoff) {
    const int tile = blockIdx.y;
    int e = -1, m0 = 0, rows = 0;
    {
        int nt = 0, prev = 0;
        #pragma unroll
        for (int ee = 0; ee < NE; ee++) {
            int end = __ldg(eoff + ee);
            int t = (end - prev + BM - 1) >> 7;
            if (e < 0 && tile < nt + t) {
                e = ee;
                m0 = prev + (tile - nt) * BM;
                int rem = end - m0;
                rows = rem < BM ? rem : BM;
            }
            nt += t;
            prev = end;
        }
    }
    if (e < 0) return;
    const int n0 = blockIdx.x * BN;

    extern __shared__ char smem[];
    const uint32_t sb = smem_u32(smem);
    const int tid  = threadIdx.x;
    const int wid  = tid >> 5;
    const int lane = tid & 31;
    const int warp_m = wid & 1;        // 2 warps along M (64 rows each)
    const int warp_n = wid >> 1;       // 2 warps along N (64 cols each)

    int* s_flat = (int*)(smem + SM_FLAT);
    if (tid < BM) s_flat[tid] = ssi[m0 + tid] | ((tid < rows) ? 0 : 0x80000000);
    __syncthreads();

    // cp.async: thread owns chunks {tid + 128q} (q=0..3) of each 512-chunk tile
    // chunk ch -> row = ch>>2, 16B col = ch&3
    const int rq   = tid >> 2;             // base row (0..31)
    const int c16  = (tid & 3) * 8;        // fp16 element offset
    const __half* aptr[4];
    const __half* bptr[4];
    uint32_t dofs[4];
    #pragma unroll
    for (int q = 0; q < 4; q++) {
        const int r = rq + 32 * q;
        const int fl = s_flat[r];
        const int tk = ((fl >= 0) ? fl : (fl & 0x7FFFFFFF)) >> 1;  // token (valid bit stripped)
        aptr[q] = g_xh + (size_t)tk * D_IN + c16;
        bptr[q] = g_wh + ((size_t)e * D_OUT + (size_t)(n0 + r)) * D_IN + c16;
        dofs[q] = SW((uint32_t)(r * 64 + (tid & 3) * 16));
    }

    // ldmatrix offsets per k16 step s: A atoms i=0..3 (16 rows), B pairs jp=0..3
    uint32_t a_off[2][4], b_off[2][4];
    #pragma unroll
    for (int s = 0; s < 2; s++) {
        #pragma unroll
        for (int i = 0; i < 4; i++) {
            int arow = warp_m * 64 + i * 16 + (lane & 7) + ((lane >> 3) & 1) * 8;
            int ach  = s * 2 + (lane >> 4);
            a_off[s][i] = SW((uint32_t)(arow * 64 + ach * 16));
        }
        #pragma unroll
        for (int jp = 0; jp < 4; jp++) {
            int brow = warp_n * 64 + (jp * 2 + (lane >> 4)) * 8 + (lane & 7);
            int bch  = s * 2 + ((lane >> 3) & 1);
            b_off[s][jp] = SW((uint32_t)(brow * 64 + bch * 16));
        }
    }

    auto issue = [&](int st, int kt) {
        const uint32_t stg = sb + SM_TILES + (uint32_t)st * STAGE_B;
        const int k = kt * KT;
        #pragma unroll
        for (int q = 0; q < 4; q++) {
            cp16(stg + T_AH + dofs[q], aptr[q] + k);
            cp16(stg + T_BH + dofs[q], bptr[q] + k);
        }
    };

    float acc[4][8][4];
    #pragma unroll
    for (int i = 0; i < 4; i++)
        #pragma unroll
        for (int j = 0; j < 8; j++)
            #pragma unroll
            for (int q = 0; q < 4; q++) acc[i][j][q] = 0.0f;

    #pragma unroll
    for (int s = 0; s < STAGES - 1; s++) { issue(s, s); cp_commit(); }

    for (int it = 0; it < NT; it++) {
        cp_wait2();
        __syncthreads();

        if (it + STAGES - 1 < NT) issue((it + STAGES - 1) & (STAGES - 1), it + STAGES - 1);
        cp_commit();

        const uint32_t stg = sb + SM_TILES + (uint32_t)(it & (STAGES - 1)) * STAGE_B;
        #pragma unroll
        for (int s = 0; s < 2; s++) {
            uint32_t ah[4][4], bh[4][4];
            #pragma unroll
            for (int i = 0; i < 4; i++)
                ldm_x4(ah[i][0], ah[i][1], ah[i][2], ah[i][3], stg + T_AH + a_off[s][i]);
            #pragma unroll
            for (int jp = 0; jp < 4; jp++)
                ldm_x4(bh[jp][0], bh[jp][1], bh[jp][2], bh[jp][3], stg + T_BH + b_off[s][jp]);
            #pragma unroll
            for (int i = 0; i < 4; i++) {
                #pragma unroll
                for (int jp = 0; jp < 4; jp++) {
                    mma_fp16(acc[i][2 * jp],     ah[i], &bh[jp][0]);
                    mma_fp16(acc[i][2 * jp + 1], ah[i], &bh[jp][2]);
                }
            }
        }
        __syncthreads();
    }

    // Epilogue: scatter to g_y
    #pragma unroll
    for (int i = 0; i < 4; i++) {
        const int mr0 = warp_m * 64 + i * 16 + (lane >> 2);
        const int fl0 = s_flat[mr0];
        const int fl1 = s_flat[mr0 + 8];
        #pragma unroll
        for (int j = 0; j < 8; j++) {
            const int col = n0 + warp_n * 64 + j * 8 + (lane & 3) * 2;
            if (fl0 >= 0)
                *(float2*)(g_y + (size_t)fl0 * D_OUT + col) =
                    make_float2(acc[i][j][0], acc[i][j][1]);
            if (fl1 >= 0)
                *(float2*)(g_y + (size_t)fl1 * D_OUT + col) =
                    make_float2(acc[i][j][2], acc[i][j][3]);
        }
    }
}

// ---------------------------------------------------------------------------
__global__ void combine_kernel(const float* __restrict__ gates,
                               float* __restrict__ out) {
    int idx = blockIdx.x * blockDim.x + threadIdx.x;
    int n  = idx >> 9;
    int d4 = idx & 511;
    float g0 = gates[2 * n];
    float g1 = gates[2 * n + 1];
    const float4* y0 = (const float4*)(g_y + (size_t)(2 * n)     * D_OUT) + d4;
    const float4* y1 = (const float4*)(g_y + (size_t)(2 * n + 1) * D_OUT) + d4;
    float4 a = *y0, b = *y1, o;
    o.x = g0 * a.x + g1 * b.x;
    o.y = g0 * a.y + g1 * b.y;
    o.z = g0 * a.z + g1 * b.z;
    o.w = g0 * a.w + g1 * b.w;
    ((float4*)out)[idx] = o;
}

// ---------------------------------------------------------------------------
extern "C" void kernel_launch(void* const* d_in, const int* in_sizes, int n_in,
                              void* d_out, int out_size) {
    const float* x     = (const float*)d_in[0];
    const float* w     = (const float*)d_in[1];
    const int*   ssi   = (const int*)  d_in[4];
    const int*   eoff  = (const int*)  d_in[6];
    const float* gates = (const float*)d_in[7];
    float* out = (float*)d_out;

    conv_x_kernel<<<(N_TOK * D_IN) / (256 * 8), 256>>>(x);
    conv_w_kernel<<<(NE * D_OUT * D_IN) / (256 * 8), 256>>>(w);

    cudaFuncSetAttribute(moe_gemm,
                         cudaFuncAttributeMaxDynamicSharedMemorySize, SMEM_TOTAL);
    dim3 grid(D_OUT / BN, MAX_TILES);
    moe_gemm<<<grid, 128, SMEM_TOTAL>>>(ssi, eoff);

    combine_kernel<<<(N_TOK * (D_OUT / 4)) / 256, 256>>>(gates, out);
}